// round 5
// baseline (speedup 1.0000x reference)
#include <cuda_runtime.h>
#include <cuda_fp16.h>
#include <math.h>
#include <stdint.h>

#define B_    8
#define Cc    384
#define Hh    112
#define Ww    112
#define HW    (Hh*Ww)
#define WS_   7
#define Nn    49
#define NH_   12
#define HD    32
#define HID_  1536
#define NW    2048
#define Tt    100352
#define EPS_  1e-5f

// ---------------- scratch (device globals) ---------------------------------
__device__ float  g_xt [(size_t)Tt * Cc];      // shortcut (window-token order) fp32
__device__ float  g_y  [(size_t)Tt * Cc];      // proj out + residual fp32
__device__ float  g_z  [(size_t)Tt * Cc];      // fc2 out + residual fp32
__device__ __half g_xn [(size_t)Tt * Cc];      // activations (ln1 / attn out / ln2) fp16
__device__ __half g_qkv[(size_t)Tt * 3 * Cc];  // fp16
__device__ __half g_h  [(size_t)Tt * HID_];    // fc1+gelu out fp16
// transposed fp16 weights, [N][K] layout
__device__ __half g_wq[1152 * 384];
__device__ __half g_wp[384 * 384];
__device__ __half g_w1[1536 * 384];
__device__ __half g_w2[384 * 1536];

// ---------------- ptx helpers ----------------------------------------------
__device__ __forceinline__ uint32_t su32(const void* p) {
    uint32_t a;
    asm("{ .reg .u64 t; cvta.to.shared.u64 t, %1; cvt.u32.u64 %0, t; }" : "=r"(a) : "l"(p));
    return a;
}
__device__ __forceinline__ void cp16(uint32_t d, const void* s) {
    asm volatile("cp.async.cg.shared.global [%0], [%1], 16;" :: "r"(d), "l"(s));
}
__device__ __forceinline__ void cp_commit() { asm volatile("cp.async.commit_group;" ::: "memory"); }
__device__ __forceinline__ void cp_wait1()  { asm volatile("cp.async.wait_group 1;" ::: "memory"); }
__device__ __forceinline__ void ldm4(uint32_t* r, uint32_t addr) {
    asm volatile("ldmatrix.sync.aligned.m8n8.x4.shared.b16 {%0,%1,%2,%3}, [%4];"
                 : "=r"(r[0]), "=r"(r[1]), "=r"(r[2]), "=r"(r[3]) : "r"(addr));
}
__device__ __forceinline__ void mma16816(float* c, const uint32_t* a, uint32_t b0, uint32_t b1) {
    asm volatile(
        "mma.sync.aligned.m16n8k16.row.col.f32.f16.f16.f32 "
        "{%0,%1,%2,%3}, {%4,%5,%6,%7}, {%8,%9}, {%0,%1,%2,%3};"
        : "+f"(c[0]), "+f"(c[1]), "+f"(c[2]), "+f"(c[3])
        : "r"(a[0]), "r"(a[1]), "r"(a[2]), "r"(a[3]), "r"(b0), "r"(b1));
}

// ---------------- transpose in ---------------------------------------------
__global__ void k_transpose_in(const float* __restrict__ x, float* __restrict__ xt)
{
    __shared__ float tile[32][33];
    int b = blockIdx.z, c0 = blockIdx.y * 32, hw0 = blockIdx.x * 32;
    const float* xb = x + (size_t)b * Cc * HW;
    #pragma unroll
    for (int i = 0; i < 32; i += 8) {
        int c = c0 + threadIdx.y + i;
        tile[threadIdx.y + i][threadIdx.x] = xb[(size_t)c * HW + hw0 + threadIdx.x];
    }
    __syncthreads();
    #pragma unroll
    for (int i = 0; i < 32; i += 8) {
        int hw = hw0 + threadIdx.y + i;
        int h = hw / Ww, w = hw % Ww;
        int t = ((b * 256 + (h / WS_) * 16 + (w / WS_)) * Nn) + (h % WS_) * WS_ + (w % WS_);
        xt[(size_t)t * Cc + c0 + threadIdx.x] = tile[threadIdx.x][threadIdx.y + i];
    }
}

// ---------------- layernorm -> fp16 ----------------------------------------
__global__ void k_ln_h(const float* __restrict__ in, const float* __restrict__ g,
                       const float* __restrict__ bt, __half* __restrict__ oh)
{
    int t = blockIdx.x * 8 + threadIdx.y;
    int lane = threadIdx.x;
    const float* row = in + (size_t)t * Cc;
    float v[12]; float s = 0.f;
    #pragma unroll
    for (int i = 0; i < 12; i++) { v[i] = row[lane + i * 32]; s += v[i]; }
    #pragma unroll
    for (int o = 16; o; o >>= 1) s += __shfl_xor_sync(0xffffffffu, s, o);
    float m = s * (1.0f / Cc);
    float s2 = 0.f;
    #pragma unroll
    for (int i = 0; i < 12; i++) { float d = v[i] - m; s2 += d * d; }
    #pragma unroll
    for (int o = 16; o; o >>= 1) s2 += __shfl_xor_sync(0xffffffffu, s2, o);
    float r = rsqrtf(s2 * (1.0f / Cc) + EPS_);
    #pragma unroll
    for (int i = 0; i < 12; i++) {
        int c = lane + i * 32;
        oh[(size_t)t * Cc + c] = __float2half_rn((v[i] - m) * r * g[c] + bt[c]);
    }
}

// ---------------- weight transpose [K][N] -> fp16 [N][K] -------------------
__global__ void k_wprep(const float* __restrict__ W, __half* __restrict__ T, int K, int N)
{
    __shared__ float tile[32][33];
    int n0 = blockIdx.x * 32, k0 = blockIdx.y * 32;
    #pragma unroll
    for (int i = 0; i < 32; i += 8) {
        int k = k0 + threadIdx.y + i, n = n0 + threadIdx.x;
        tile[threadIdx.y + i][threadIdx.x] = W[(size_t)k * N + n];
    }
    __syncthreads();
    #pragma unroll
    for (int i = 0; i < 32; i += 8) {
        int n = n0 + threadIdx.y + i, k = k0 + threadIdx.x;
        T[(size_t)n * K + k] = __float2half_rn(tile[threadIdx.x][threadIdx.y + i]);
    }
}

// ---------------- HMMA GEMM: 128x128 tile, fp16 in, fp32 accum -------------
// EPI: 0 = bias -> fp16 out ; 1 = bias + residual -> fp32 out ; 2 = bias+gelu -> fp16 out
__device__ __forceinline__ void load_stage(uint32_t sb, int s, int kc,
    const __half* __restrict__ A, const __half* __restrict__ Bw,
    int m0, int n0, int K, int tid)
{
    uint32_t base = sb + s * 32768;
    #pragma unroll
    for (int i = 0; i < 4; i++) {
        int e = tid + i * 256;          // 0..1023
        int r = e >> 3, c = e & 7;
        uint32_t so = (uint32_t)(r * 128 + ((c ^ (r & 7)) << 4));
        cp16(base + so,         A  + (size_t)(m0 + r) * K + kc + c * 8);
        cp16(base + 16384 + so, Bw + (size_t)(n0 + r) * K + kc + c * 8);
    }
    cp_commit();
}

template<int EPI>
__global__ void __launch_bounds__(256, 1) k_hgemm(
    const __half* __restrict__ A, const __half* __restrict__ Bw,
    const float* __restrict__ bias, const float* __restrict__ res,
    float* __restrict__ outf, __half* __restrict__ outh,
    int N, int K)
{
    extern __shared__ char dsm[];
    uint32_t sb = su32(dsm);
    int tid = threadIdx.x, lane = tid & 31, wid = tid >> 5;
    int m0 = blockIdx.y * 128, n0 = blockIdx.x * 128;
    int wm = (wid & 1) * 64, wn = (wid >> 1) * 32;

    float acc[4][4][4];
    #pragma unroll
    for (int i = 0; i < 4; i++)
        #pragma unroll
        for (int j = 0; j < 4; j++)
            #pragma unroll
            for (int q = 0; q < 4; q++) acc[i][j][q] = 0.f;

    load_stage(sb, 0, 0,  A, Bw, m0, n0, K, tid);
    load_stage(sb, 1, 64, A, Bw, m0, n0, K, tid);

    int nt = K >> 6;
    for (int t = 0; t < nt; t++) {
        int cur = t & 1;
        cp_wait1();
        __syncthreads();
        uint32_t abase = sb + cur * 32768;
        uint32_t bbase = abase + 16384;
        #pragma unroll
        for (int s = 0; s < 4; s++) {
            uint32_t a[4][4], b[2][4];
            #pragma unroll
            for (int mi = 0; mi < 4; mi++) {
                int r = wm + mi * 16 + (lane & 15);
                int c = 2 * s + (lane >> 4);
                ldm4(a[mi], abase + r * 128 + ((c ^ (r & 7)) << 4));
            }
            #pragma unroll
            for (int bi = 0; bi < 2; bi++) {
                int r = wn + bi * 16 + (lane & 15);
                int c = 2 * s + (lane >> 4);
                ldm4(b[bi], bbase + r * 128 + ((c ^ (r & 7)) << 4));
            }
            #pragma unroll
            for (int mi = 0; mi < 4; mi++)
                #pragma unroll
                for (int ni = 0; ni < 4; ni++)
                    mma16816(acc[mi][ni], a[mi], b[ni >> 1][ni & 1], b[ni >> 1][(ni & 1) + 2]);
        }
        __syncthreads();
        if (t + 2 < nt) load_stage(sb, cur, (t + 2) * 64, A, Bw, m0, n0, K, tid);
        else cp_commit();
    }

    // epilogue: direct register -> gmem (32B segments fully covered per quad)
    #pragma unroll
    for (int mi = 0; mi < 4; mi++) {
        #pragma unroll
        for (int ni = 0; ni < 4; ni++) {
            int m = m0 + wm + mi * 16 + (lane >> 2);
            int n = n0 + wn + ni * 8 + 2 * (lane & 3);
            float b0 = bias[n], b1 = bias[n + 1];
            float v0 = acc[mi][ni][0] + b0, v1 = acc[mi][ni][1] + b1;
            float v2 = acc[mi][ni][2] + b0, v3 = acc[mi][ni][3] + b1;
            size_t off0 = (size_t)m * N + n;
            size_t off1 = (size_t)(m + 8) * N + n;
            if (EPI == 2) {
                v0 = 0.5f * v0 * (1.0f + erff(v0 * 0.70710678118654752f));
                v1 = 0.5f * v1 * (1.0f + erff(v1 * 0.70710678118654752f));
                v2 = 0.5f * v2 * (1.0f + erff(v2 * 0.70710678118654752f));
                v3 = 0.5f * v3 * (1.0f + erff(v3 * 0.70710678118654752f));
            }
            if (EPI == 1) {
                float2 r0 = *(const float2*)&res[off0];
                float2 r1 = *(const float2*)&res[off1];
                *(float2*)&outf[off0] = make_float2(v0 + r0.x, v1 + r0.y);
                *(float2*)&outf[off1] = make_float2(v2 + r1.x, v3 + r1.y);
            } else {
                *(__half2*)&outh[off0] = __floats2half2_rn(v0, v1);
                *(__half2*)&outh[off1] = __floats2half2_rn(v2, v3);
            }
        }
    }
}

// ---------------- window attention (fp16 in/out, fp32 math) ----------------
__global__ void __launch_bounds__(64) k_attn(const __half* __restrict__ qkv,
                                             const float* __restrict__ rpb,
                                             __half* __restrict__ oh)
{
    int wb = blockIdx.x, hh = blockIdx.y;
    __shared__ float qs[Nn * 33];
    __shared__ float ks[Nn * 33];
    __shared__ float vs[Nn * 33];
    __shared__ float srpb[169];
    int tid = threadIdx.x;

    for (int i = tid; i < 169; i += 64) srpb[i] = rpb[i * NH_ + hh];
    size_t base = (size_t)wb * Nn * (3 * Cc) + hh * HD;
    for (int e = tid; e < Nn * 16; e += 64) {
        int p = e >> 4, d2 = (e & 15) * 2;
        size_t rowp = base + (size_t)p * (3 * Cc);
        __half2 hq = *(const __half2*)&qkv[rowp + d2];
        __half2 hk = *(const __half2*)&qkv[rowp + Cc + d2];
        __half2 hv = *(const __half2*)&qkv[rowp + 2 * Cc + d2];
        float2 fq = __half22float2(hq), fk = __half22float2(hk), fv = __half22float2(hv);
        qs[p * 33 + d2] = fq.x; qs[p * 33 + d2 + 1] = fq.y;
        ks[p * 33 + d2] = fk.x; ks[p * 33 + d2 + 1] = fk.y;
        vs[p * 33 + d2] = fv.x; vs[p * 33 + d2 + 1] = fv.y;
    }
    __syncthreads();

    if (tid < Nn) {
        int n = tid;
        int r1 = n / WS_, s1 = n % WS_;
        float q[HD];
        #pragma unroll
        for (int d = 0; d < HD; d++) q[d] = qs[n * 33 + d] * 0.17677669529663687f;
        float s[Nn]; float mx = -1e30f;
        #pragma unroll
        for (int m = 0; m < Nn; m++) {
            float a = 0.f;
            #pragma unroll
            for (int d = 0; d < HD; d++) a += q[d] * ks[m * 33 + d];
            int r2 = m / WS_, s2 = m % WS_;
            a += srpb[(r1 - r2 + 6) * 13 + (s1 - s2 + 6)];
            s[m] = a; mx = fmaxf(mx, a);
        }
        float sum = 0.f;
        #pragma unroll
        for (int m = 0; m < Nn; m++) { s[m] = __expf(s[m] - mx); sum += s[m]; }
        float inv = 1.0f / sum;
        float o[HD];
        #pragma unroll
        for (int d = 0; d < HD; d++) o[d] = 0.f;
        #pragma unroll
        for (int m = 0; m < Nn; m++) {
            float p = s[m] * inv;
            #pragma unroll
            for (int d = 0; d < HD; d++) o[d] += p * vs[m * 33 + d];
        }
        size_t orow = (size_t)(wb * Nn + n) * Cc + hh * HD;
        #pragma unroll
        for (int d = 0; d < HD; d += 2)
            *(__half2*)&oh[orow + d] = __floats2half2_rn(o[d], o[d + 1]);
    }
}

// ---------------- transpose out --------------------------------------------
__global__ void k_transpose_out(const float* __restrict__ z, float* __restrict__ out)
{
    __shared__ float sm[Nn][33];
    int wb = blockIdx.x, c0 = blockIdx.y * 32;
    int b = wb >> 8, wi = (wb >> 4) & 15, wj = wb & 15;
    int tid = threadIdx.x;
    for (int e = tid; e < Nn * 32; e += 256) {
        int p = e >> 5, d = e & 31;
        sm[p][d] = z[(size_t)(wb * Nn + p) * Cc + c0 + d];
    }
    __syncthreads();
    for (int e = tid; e < Nn * 32; e += 256) {
        int d = e / Nn, p = e % Nn;
        int c = c0 + d;
        int h = wi * WS_ + p / WS_, w = wj * WS_ + p % WS_;
        out[(((size_t)b * Cc + c) * Hh + h) * Ww + w] = sm[p][d];
    }
}

// ---------------- launch ----------------------------------------------------
extern "C" void kernel_launch(void* const* d_in, const int* in_sizes, int n_in,
                              void* d_out, int out_size)
{
    const float* x      = (const float*)d_in[0];
    const float* g1     = (const float*)d_in[1];
    const float* b1     = (const float*)d_in[2];
    const float* w_qkv  = (const float*)d_in[3];
    const float* b_qkv  = (const float*)d_in[4];
    const float* rpb    = (const float*)d_in[5];
    const float* w_proj = (const float*)d_in[6];
    const float* b_proj = (const float*)d_in[7];
    const float* g2     = (const float*)d_in[8];
    const float* b2     = (const float*)d_in[9];
    const float* w_fc1  = (const float*)d_in[10];
    const float* b_fc1  = (const float*)d_in[11];
    const float* w_fc2  = (const float*)d_in[12];
    const float* b_fc2  = (const float*)d_in[13];
    float* out = (float*)d_out;

    float *xt, *y, *z;
    __half *xn, *qkv, *hbuf, *wq, *wp, *w1, *w2;
    cudaGetSymbolAddress((void**)&xt, g_xt);
    cudaGetSymbolAddress((void**)&y, g_y);
    cudaGetSymbolAddress((void**)&z, g_z);
    cudaGetSymbolAddress((void**)&xn, g_xn);
    cudaGetSymbolAddress((void**)&qkv, g_qkv);
    cudaGetSymbolAddress((void**)&hbuf, g_h);
    cudaGetSymbolAddress((void**)&wq, g_wq);
    cudaGetSymbolAddress((void**)&wp, g_wp);
    cudaGetSymbolAddress((void**)&w1, g_w1);
    cudaGetSymbolAddress((void**)&w2, g_w2);

    const int SMEM = 65536;
    cudaFuncSetAttribute(k_hgemm<0>, cudaFuncAttributeMaxDynamicSharedMemorySize, SMEM);
    cudaFuncSetAttribute(k_hgemm<1>, cudaFuncAttributeMaxDynamicSharedMemorySize, SMEM);
    cudaFuncSetAttribute(k_hgemm<2>, cudaFuncAttributeMaxDynamicSharedMemorySize, SMEM);

    // weight prep (transpose + fp16)
    k_wprep<<<dim3(1152 / 32, 384 / 32), dim3(32, 8)>>>(w_qkv, wq, 384, 1152);
    k_wprep<<<dim3(384 / 32, 384 / 32), dim3(32, 8)>>>(w_proj, wp, 384, 384);
    k_wprep<<<dim3(1536 / 32, 384 / 32), dim3(32, 8)>>>(w_fc1, w1, 384, 1536);
    k_wprep<<<dim3(384 / 32, 1536 / 32), dim3(32, 8)>>>(w_fc2, w2, 1536, 384);

    // 1. transpose + window partition
    k_transpose_in<<<dim3(HW / 32, Cc / 32, B_), dim3(32, 8)>>>(x, xt);
    // 2. LN1 -> fp16
    k_ln_h<<<Tt / 8, dim3(32, 8)>>>(xt, g1, b1, xn);
    // 3. QKV GEMM (fp16 out)
    k_hgemm<0><<<dim3(9, Tt / 128), 256, SMEM>>>(xn, wq, b_qkv, nullptr, nullptr, qkv, 1152, 384);
    // 4. attention -> fp16 (reuse xn)
    k_attn<<<dim3(NW, NH_), 64>>>(qkv, rpb, xn);
    // 5. proj GEMM + residual(xt) -> y fp32
    k_hgemm<1><<<dim3(3, Tt / 128), 256, SMEM>>>(xn, wp, b_proj, xt, y, nullptr, 384, 384);
    // 6. LN2 -> fp16
    k_ln_h<<<Tt / 8, dim3(32, 8)>>>(y, g2, b2, xn);
    // 7. fc1 GEMM + gelu -> fp16
    k_hgemm<2><<<dim3(12, Tt / 128), 256, SMEM>>>(xn, w1, b_fc1, nullptr, nullptr, hbuf, 1536, 384);
    // 8. fc2 GEMM + residual(y) -> z fp32
    k_hgemm<1><<<dim3(3, Tt / 128), 256, SMEM>>>(hbuf, w2, b_fc2, y, z, nullptr, 384, 1536);
    // 9. transpose back
    k_transpose_out<<<dim3(NW, Cc / 32), 256>>>(z, out);
}

// round 10
// speedup vs baseline: 1.2250x; 1.2250x over previous
#include <cuda_runtime.h>
#include <cuda_fp16.h>
#include <math.h>
#include <stdint.h>

#define B_    8
#define Cc    384
#define Hh    112
#define Ww    112
#define HW    (Hh*Ww)
#define WS_   7
#define Nn    49
#define NH_   12
#define HD    32
#define HID_  1536
#define NW    2048
#define Tt    100352
#define EPS_  1e-5f

// ---------------- scratch (device globals) ---------------------------------
__device__ float  g_xt [(size_t)Tt * Cc];
__device__ float  g_y  [(size_t)Tt * Cc];
__device__ float  g_z  [(size_t)Tt * Cc];
__device__ __half g_xn [(size_t)Tt * Cc];
__device__ __half g_qkv[(size_t)Tt * 3 * Cc];
__device__ __half g_h  [(size_t)Tt * HID_];
__device__ __half g_wq[1152 * 384];
__device__ __half g_wp[384 * 384];
__device__ __half g_w1[1536 * 384];
__device__ __half g_w2[384 * 1536];

// ---------------- ptx helpers ----------------------------------------------
__device__ __forceinline__ uint32_t su32(const void* p) {
    uint32_t a;
    asm("{ .reg .u64 t; cvta.to.shared.u64 t, %1; cvt.u32.u64 %0, t; }" : "=r"(a) : "l"(p));
    return a;
}
__device__ __forceinline__ uint32_t h2u(__half2 h) {
    return *reinterpret_cast<uint32_t*>(&h);
}
__device__ __forceinline__ void cp16(uint32_t d, const void* s) {
    asm volatile("cp.async.cg.shared.global [%0], [%1], 16;" :: "r"(d), "l"(s));
}
__device__ __forceinline__ void cp_commit() { asm volatile("cp.async.commit_group;" ::: "memory"); }
__device__ __forceinline__ void cp_wait2()  { asm volatile("cp.async.wait_group 2;" ::: "memory"); }
__device__ __forceinline__ void cp_wait0()  { asm volatile("cp.async.wait_group 0;" ::: "memory"); }
__device__ __forceinline__ void ldm4(uint32_t* r, uint32_t addr) {
    asm volatile("ldmatrix.sync.aligned.m8n8.x4.shared.b16 {%0,%1,%2,%3}, [%4];"
                 : "=r"(r[0]), "=r"(r[1]), "=r"(r[2]), "=r"(r[3]) : "r"(addr));
}
__device__ __forceinline__ void ldm4t(uint32_t* r, uint32_t addr) {
    asm volatile("ldmatrix.sync.aligned.m8n8.x4.trans.shared.b16 {%0,%1,%2,%3}, [%4];"
                 : "=r"(r[0]), "=r"(r[1]), "=r"(r[2]), "=r"(r[3]) : "r"(addr));
}
__device__ __forceinline__ void mma16816(float* c, const uint32_t* a, uint32_t b0, uint32_t b1) {
    asm volatile(
        "mma.sync.aligned.m16n8k16.row.col.f32.f16.f16.f32 "
        "{%0,%1,%2,%3}, {%4,%5,%6,%7}, {%8,%9}, {%0,%1,%2,%3};"
        : "+f"(c[0]), "+f"(c[1]), "+f"(c[2]), "+f"(c[3])
        : "r"(a[0]), "r"(a[1]), "r"(a[2]), "r"(a[3]), "r"(b0), "r"(b1));
}
__device__ __forceinline__ int div7(int x) { return (x * 9363) >> 16; }

// ---------------- transpose in ---------------------------------------------
__global__ void k_transpose_in(const float* __restrict__ x, float* __restrict__ xt)
{
    __shared__ float tile[32][33];
    int b = blockIdx.z, c0 = blockIdx.y * 32, hw0 = blockIdx.x * 32;
    const float* xb = x + (size_t)b * Cc * HW;
    #pragma unroll
    for (int i = 0; i < 32; i += 8) {
        int c = c0 + threadIdx.y + i;
        tile[threadIdx.y + i][threadIdx.x] = xb[(size_t)c * HW + hw0 + threadIdx.x];
    }
    __syncthreads();
    #pragma unroll
    for (int i = 0; i < 32; i += 8) {
        int hw = hw0 + threadIdx.y + i;
        int h = hw / Ww, w = hw % Ww;
        int t = ((b * 256 + (h / WS_) * 16 + (w / WS_)) * Nn) + (h % WS_) * WS_ + (w % WS_);
        xt[(size_t)t * Cc + c0 + threadIdx.x] = tile[threadIdx.x][threadIdx.y + i];
    }
}

// ---------------- layernorm -> fp16 ----------------------------------------
__global__ void k_ln_h(const float* __restrict__ in, const float* __restrict__ g,
                       const float* __restrict__ bt, __half* __restrict__ oh)
{
    int t = blockIdx.x * 8 + threadIdx.y;
    int lane = threadIdx.x;
    const float* row = in + (size_t)t * Cc;
    float v[12]; float s = 0.f;
    #pragma unroll
    for (int i = 0; i < 12; i++) { v[i] = row[lane + i * 32]; s += v[i]; }
    #pragma unroll
    for (int o = 16; o; o >>= 1) s += __shfl_xor_sync(0xffffffffu, s, o);
    float m = s * (1.0f / Cc);
    float s2 = 0.f;
    #pragma unroll
    for (int i = 0; i < 12; i++) { float d = v[i] - m; s2 += d * d; }
    #pragma unroll
    for (int o = 16; o; o >>= 1) s2 += __shfl_xor_sync(0xffffffffu, s2, o);
    float r = rsqrtf(s2 * (1.0f / Cc) + EPS_);
    #pragma unroll
    for (int i = 0; i < 12; i++) {
        int c = lane + i * 32;
        oh[(size_t)t * Cc + c] = __float2half_rn((v[i] - m) * r * g[c] + bt[c]);
    }
}

// ---------------- weight transpose [K][N] -> fp16 [N][K] -------------------
__global__ void k_wprep(const float* __restrict__ W, __half* __restrict__ T, int K, int N)
{
    __shared__ float tile[32][33];
    int n0 = blockIdx.x * 32, k0 = blockIdx.y * 32;
    #pragma unroll
    for (int i = 0; i < 32; i += 8) {
        int k = k0 + threadIdx.y + i, n = n0 + threadIdx.x;
        tile[threadIdx.y + i][threadIdx.x] = W[(size_t)k * N + n];
    }
    __syncthreads();
    #pragma unroll
    for (int i = 0; i < 32; i += 8) {
        int n = n0 + threadIdx.y + i, k = k0 + threadIdx.x;
        T[(size_t)n * K + k] = __float2half_rn(tile[threadIdx.x][threadIdx.y + i]);
    }
}

// ---------------- HMMA GEMM: 128x128 tile, 3-stage pipeline ----------------
__device__ __forceinline__ void load_stage(uint32_t sb, int s, int kc,
    const __half* __restrict__ A, const __half* __restrict__ Bw,
    int m0, int n0, int K, int tid)
{
    uint32_t base = sb + s * 32768;
    #pragma unroll
    for (int i = 0; i < 4; i++) {
        int e = tid + i * 256;
        int r = e >> 3, c = e & 7;
        uint32_t so = (uint32_t)(r * 128 + ((c ^ (r & 7)) << 4));
        cp16(base + so,         A  + (size_t)(m0 + r) * K + kc + c * 8);
        cp16(base + 16384 + so, Bw + (size_t)(n0 + r) * K + kc + c * 8);
    }
    cp_commit();
}

template<int EPI>
__global__ void __launch_bounds__(256, 1) k_hgemm(
    const __half* __restrict__ A, const __half* __restrict__ Bw,
    const float* __restrict__ bias, const float* __restrict__ res,
    float* __restrict__ outf, __half* __restrict__ outh,
    int N, int K)
{
    extern __shared__ char dsm[];
    uint32_t sb = su32(dsm);
    int tid = threadIdx.x, lane = tid & 31, wid = tid >> 5;
    int m0 = blockIdx.y * 128, n0 = blockIdx.x * 128;
    int wm = (wid & 1) * 64, wn = (wid >> 1) * 32;

    float acc[4][4][4];
    #pragma unroll
    for (int i = 0; i < 4; i++)
        #pragma unroll
        for (int j = 0; j < 4; j++)
            #pragma unroll
            for (int q = 0; q < 4; q++) acc[i][j][q] = 0.f;

    load_stage(sb, 0, 0,   A, Bw, m0, n0, K, tid);
    load_stage(sb, 1, 64,  A, Bw, m0, n0, K, tid);
    load_stage(sb, 2, 128, A, Bw, m0, n0, K, tid);

    int nt = K >> 6;
    int cur = 0;
    for (int t = 0; t < nt; t++) {
        cp_wait2();
        __syncthreads();
        uint32_t abase = sb + cur * 32768;
        uint32_t bbase = abase + 16384;
        #pragma unroll
        for (int s = 0; s < 4; s++) {
            uint32_t a[4][4], b[2][4];
            #pragma unroll
            for (int mi = 0; mi < 4; mi++) {
                int r = wm + mi * 16 + (lane & 15);
                int c = 2 * s + (lane >> 4);
                ldm4(a[mi], abase + r * 128 + ((c ^ (r & 7)) << 4));
            }
            #pragma unroll
            for (int bi = 0; bi < 2; bi++) {
                int r = wn + bi * 16 + (lane & 15);
                int c = 2 * s + (lane >> 4);
                ldm4(b[bi], bbase + r * 128 + ((c ^ (r & 7)) << 4));
            }
            #pragma unroll
            for (int mi = 0; mi < 4; mi++)
                #pragma unroll
                for (int ni = 0; ni < 4; ni++)
                    mma16816(acc[mi][ni], a[mi], b[ni >> 1][ni & 1], b[ni >> 1][(ni & 1) + 2]);
        }
        __syncthreads();
        if (t + 3 < nt) load_stage(sb, cur, (t + 3) * 64, A, Bw, m0, n0, K, tid);
        else cp_commit();
        cur = (cur == 2) ? 0 : cur + 1;
    }

    #pragma unroll
    for (int mi = 0; mi < 4; mi++) {
        #pragma unroll
        for (int ni = 0; ni < 4; ni++) {
            int m = m0 + wm + mi * 16 + (lane >> 2);
            int n = n0 + wn + ni * 8 + 2 * (lane & 3);
            float b0 = bias[n], b1 = bias[n + 1];
            float v0 = acc[mi][ni][0] + b0, v1 = acc[mi][ni][1] + b1;
            float v2 = acc[mi][ni][2] + b0, v3 = acc[mi][ni][3] + b1;
            size_t off0 = (size_t)m * N + n;
            size_t off1 = (size_t)(m + 8) * N + n;
            if (EPI == 2) {
                v0 = 0.5f * v0 * (1.0f + erff(v0 * 0.70710678118654752f));
                v1 = 0.5f * v1 * (1.0f + erff(v1 * 0.70710678118654752f));
                v2 = 0.5f * v2 * (1.0f + erff(v2 * 0.70710678118654752f));
                v3 = 0.5f * v3 * (1.0f + erff(v3 * 0.70710678118654752f));
            }
            if (EPI == 1) {
                float2 r0 = *(const float2*)&res[off0];
                float2 r1 = *(const float2*)&res[off1];
                *(float2*)&outf[off0] = make_float2(v0 + r0.x, v1 + r0.y);
                *(float2*)&outf[off1] = make_float2(v2 + r1.x, v3 + r1.y);
            } else {
                *(__half2*)&outh[off0] = __floats2half2_rn(v0, v1);
                *(__half2*)&outh[off1] = __floats2half2_rn(v2, v3);
            }
        }
    }
}

// ---------------- tensor-core window attention ------------------------------
// block = 128 threads (4 warps) per (window, head); warp w owns rows [16w,16w+16)
// smem: Q,K,V fp16 64x32 swizzled (4KB each) + rpb fp32 169
__global__ void __launch_bounds__(128) k_attn(const __half* __restrict__ qkv,
                                              const float* __restrict__ rpb,
                                              __half* __restrict__ oh)
{
    __shared__ __align__(128) char sm[12288 + 680];
    float* srpb = (float*)(sm + 12288);
    int wb = blockIdx.x, head = blockIdx.y;
    int tid = threadIdx.x, lane = tid & 31, warp = tid >> 5;
    uint32_t sb = su32(sm);

    // fill Q/K/V (rows 0-48) via cp.async; zero pad rows 49-63
    for (int i = tid; i < 588; i += 128) {
        int mat = i / 196;
        int rem = i - mat * 196;
        int r = rem >> 2, c = rem & 3;
        const __half* src = qkv + ((size_t)(wb * Nn + r)) * 1152 + mat * 384 + head * 32 + c * 8;
        cp16(sb + mat * 4096 + r * 64 + ((c ^ ((r >> 1) & 3)) << 4), src);
    }
    cp_commit();
    uint4 z4 = make_uint4(0, 0, 0, 0);
    for (int i = tid; i < 180; i += 128) {
        int mat = i / 60;
        int rem = i - mat * 60;
        int r = 49 + (rem >> 2), c = rem & 3;
        *(uint4*)(sm + mat * 4096 + r * 64 + ((c ^ ((r >> 1) & 3)) << 4)) = z4;
    }
    for (int i = tid; i < 169; i += 128) srpb[i] = rpb[i * NH_ + head];
    cp_wait0();
    __syncthreads();

    uint32_t qbase = sb, kbase = sb + 4096, vbase = sb + 8192;
    int m0 = warp * 16;

    // ---- S = Q K^T : 8 n-tiles, 2 k-steps ----
    float sc[8][4];
    #pragma unroll
    for (int j = 0; j < 8; j++)
        #pragma unroll
        for (int q = 0; q < 4; q++) sc[j][q] = 0.f;

    #pragma unroll
    for (int ks = 0; ks < 2; ks++) {
        uint32_t qa[4];
        {
            int g = lane >> 3;
            int r = m0 + (lane & 7) + ((g & 1) ? 8 : 0);
            int c = 2 * ks + (g >> 1);
            ldm4(qa, qbase + r * 64 + ((c ^ ((r >> 1) & 3)) << 4));
        }
        #pragma unroll
        for (int jj = 0; jj < 4; jj++) {  // pairs of n-tiles
            uint32_t kb[4];
            {
                int g = lane >> 3;
                int r = (2 * jj + (g >> 1)) * 8 + (lane & 7);  // key row
                int c = 2 * ks + (g & 1);
                ldm4(kb, kbase + r * 64 + ((c ^ ((r >> 1) & 3)) << 4));
            }
            mma16816(sc[2 * jj],     qa, kb[0], kb[1]);
            mma16816(sc[2 * jj + 1], qa, kb[2], kb[3]);
        }
    }

    // ---- scale + bias + mask ----
    int R0 = m0 + (lane >> 2);
    int R1 = R0 + 8;
    int r1a = 0, s1a = 0, r1b = 0, s1b = 0;
    if (R0 < Nn) { r1a = div7(R0); s1a = R0 - 7 * r1a; }
    if (R1 < Nn) { r1b = div7(R1); s1b = R1 - 7 * r1b; }
    const float SC = 0.17677669529663687f;
    #pragma unroll
    for (int j = 0; j < 8; j++) {
        #pragma unroll
        for (int e = 0; e < 2; e++) {
            int col = 8 * j + 2 * (lane & 3) + e;
            float ba, bb;
            if (col < Nn) {
                int r2 = div7(col), s2 = col - 7 * r2;
                ba = srpb[(r1a - r2 + 6) * 13 + (s1a - s2 + 6)];
                bb = srpb[(r1b - r2 + 6) * 13 + (s1b - s2 + 6)];
            } else { ba = -30000.f; bb = -30000.f; }
            sc[j][e]     = sc[j][e] * SC + ba;
            sc[j][e + 2] = sc[j][e + 2] * SC + bb;
        }
    }

    // ---- softmax (rows R0, R1), unnormalized probs to fp16 ----
    float mx0 = -1e30f, mx1 = -1e30f;
    #pragma unroll
    for (int j = 0; j < 8; j++) {
        mx0 = fmaxf(mx0, fmaxf(sc[j][0], sc[j][1]));
        mx1 = fmaxf(mx1, fmaxf(sc[j][2], sc[j][3]));
    }
    mx0 = fmaxf(mx0, __shfl_xor_sync(0xffffffffu, mx0, 1));
    mx0 = fmaxf(mx0, __shfl_xor_sync(0xffffffffu, mx0, 2));
    mx1 = fmaxf(mx1, __shfl_xor_sync(0xffffffffu, mx1, 1));
    mx1 = fmaxf(mx1, __shfl_xor_sync(0xffffffffu, mx1, 2));
    float sm0 = 0.f, sm1 = 0.f;
    #pragma unroll
    for (int j = 0; j < 8; j++) {
        sc[j][0] = __expf(sc[j][0] - mx0);
        sc[j][1] = __expf(sc[j][1] - mx0);
        sc[j][2] = __expf(sc[j][2] - mx1);
        sc[j][3] = __expf(sc[j][3] - mx1);
        sm0 += sc[j][0] + sc[j][1];
        sm1 += sc[j][2] + sc[j][3];
    }
    sm0 += __shfl_xor_sync(0xffffffffu, sm0, 1);
    sm0 += __shfl_xor_sync(0xffffffffu, sm0, 2);
    sm1 += __shfl_xor_sync(0xffffffffu, sm1, 1);
    sm1 += __shfl_xor_sync(0xffffffffu, sm1, 2);

    uint32_t pa[4][4];
    #pragma unroll
    for (int t = 0; t < 4; t++) {
        pa[t][0] = h2u(__floats2half2_rn(sc[2 * t][0], sc[2 * t][1]));
        pa[t][1] = h2u(__floats2half2_rn(sc[2 * t][2], sc[2 * t][3]));
        pa[t][2] = h2u(__floats2half2_rn(sc[2 * t + 1][0], sc[2 * t + 1][1]));
        pa[t][3] = h2u(__floats2half2_rn(sc[2 * t + 1][2], sc[2 * t + 1][3]));
    }

    // ---- O = P V : 4 k-steps (keys), 4 n-tiles (dims) ----
    float o[4][4];
    #pragma unroll
    for (int j = 0; j < 4; j++)
        #pragma unroll
        for (int q = 0; q < 4; q++) o[j][q] = 0.f;
    #pragma unroll
    for (int t = 0; t < 4; t++) {
        #pragma unroll
        for (int jj = 0; jj < 2; jj++) {  // pairs of n-tiles
            uint32_t vb[4];
            {
                int g = lane >> 3;
                int r = 16 * t + ((g & 1) ? 8 : 0) + (lane & 7);  // key row
                int c = 2 * jj + (g >> 1);                          // dim chunk
                ldm4t(vb, vbase + r * 64 + ((c ^ ((r >> 1) & 3)) << 4));
            }
            mma16816(o[2 * jj],     pa[t], vb[0], vb[1]);
            mma16816(o[2 * jj + 1], pa[t], vb[2], vb[3]);
        }
    }

    // ---- normalize + store rows < 49 ----
    float inv0 = 1.0f / sm0, inv1 = 1.0f / sm1;
    #pragma unroll
    for (int j = 0; j < 4; j++) {
        int col = 8 * j + 2 * (lane & 3);
        if (R0 < Nn) {
            size_t off = (size_t)(wb * Nn + R0) * Cc + head * HD + col;
            *(__half2*)&oh[off] = __floats2half2_rn(o[j][0] * inv0, o[j][1] * inv0);
        }
        if (R1 < Nn) {
            size_t off = (size_t)(wb * Nn + R1) * Cc + head * HD + col;
            *(__half2*)&oh[off] = __floats2half2_rn(o[j][2] * inv1, o[j][3] * inv1);
        }
    }
}

// ---------------- transpose out --------------------------------------------
__global__ void k_transpose_out(const float* __restrict__ z, float* __restrict__ out)
{
    __shared__ float sm[Nn][33];
    int wb = blockIdx.x, c0 = blockIdx.y * 32;
    int b = wb >> 8, wi = (wb >> 4) & 15, wj = wb & 15;
    int tid = threadIdx.x;
    for (int e = tid; e < Nn * 32; e += 256) {
        int p = e >> 5, d = e & 31;
        sm[p][d] = z[(size_t)(wb * Nn + p) * Cc + c0 + d];
    }
    __syncthreads();
    for (int e = tid; e < Nn * 32; e += 256) {
        int d = e / Nn, p = e % Nn;
        int c = c0 + d;
        int h = wi * WS_ + p / WS_, w = wj * WS_ + p % WS_;
        out[(((size_t)b * Cc + c) * Hh + h) * Ww + w] = sm[p][d];
    }
}

// ---------------- launch ----------------------------------------------------
extern "C" void kernel_launch(void* const* d_in, const int* in_sizes, int n_in,
                              void* d_out, int out_size)
{
    const float* x      = (const float*)d_in[0];
    const float* g1     = (const float*)d_in[1];
    const float* b1     = (const float*)d_in[2];
    const float* w_qkv  = (const float*)d_in[3];
    const float* b_qkv  = (const float*)d_in[4];
    const float* rpb    = (const float*)d_in[5];
    const float* w_proj = (const float*)d_in[6];
    const float* b_proj = (const float*)d_in[7];
    const float* g2     = (const float*)d_in[8];
    const float* b2     = (const float*)d_in[9];
    const float* w_fc1  = (const float*)d_in[10];
    const float* b_fc1  = (const float*)d_in[11];
    const float* w_fc2  = (const float*)d_in[12];
    const float* b_fc2  = (const float*)d_in[13];
    float* out = (float*)d_out;

    float *xt, *y, *z;
    __half *xn, *qkv, *hbuf, *wq, *wp, *w1, *w2;
    cudaGetSymbolAddress((void**)&xt, g_xt);
    cudaGetSymbolAddress((void**)&y, g_y);
    cudaGetSymbolAddress((void**)&z, g_z);
    cudaGetSymbolAddress((void**)&xn, g_xn);
    cudaGetSymbolAddress((void**)&qkv, g_qkv);
    cudaGetSymbolAddress((void**)&hbuf, g_h);
    cudaGetSymbolAddress((void**)&wq, g_wq);
    cudaGetSymbolAddress((void**)&wp, g_wp);
    cudaGetSymbolAddress((void**)&w1, g_w1);
    cudaGetSymbolAddress((void**)&w2, g_w2);

    const int SMEM = 3 * 32768;
    cudaFuncSetAttribute(k_hgemm<0>, cudaFuncAttributeMaxDynamicSharedMemorySize, SMEM);
    cudaFuncSetAttribute(k_hgemm<1>, cudaFuncAttributeMaxDynamicSharedMemorySize, SMEM);
    cudaFuncSetAttribute(k_hgemm<2>, cudaFuncAttributeMaxDynamicSharedMemorySize, SMEM);

    k_wprep<<<dim3(1152 / 32, 384 / 32), dim3(32, 8)>>>(w_qkv, wq, 384, 1152);
    k_wprep<<<dim3(384 / 32, 384 / 32), dim3(32, 8)>>>(w_proj, wp, 384, 384);
    k_wprep<<<dim3(1536 / 32, 384 / 32), dim3(32, 8)>>>(w_fc1, w1, 384, 1536);
    k_wprep<<<dim3(384 / 32, 1536 / 32), dim3(32, 8)>>>(w_fc2, w2, 1536, 384);

    k_transpose_in<<<dim3(HW / 32, Cc / 32, B_), dim3(32, 8)>>>(x, xt);
    k_ln_h<<<Tt / 8, dim3(32, 8)>>>(xt, g1, b1, xn);
    k_hgemm<0><<<dim3(9, Tt / 128), 256, SMEM>>>(xn, wq, b_qkv, nullptr, nullptr, qkv, 1152, 384);
    k_attn<<<dim3(NW, NH_), 128>>>(qkv, rpb, xn);
    k_hgemm<1><<<dim3(3, Tt / 128), 256, SMEM>>>(xn, wp, b_proj, xt, y, nullptr, 384, 384);
    k_ln_h<<<Tt / 8, dim3(32, 8)>>>(y, g2, b2, xn);
    k_hgemm<2><<<dim3(12, Tt / 128), 256, SMEM>>>(xn, w1, b_fc1, nullptr, nullptr, hbuf, 1536, 384);
    k_hgemm<1><<<dim3(3, Tt / 128), 256, SMEM>>>(hbuf, w2, b_fc2, y, z, nullptr, 384, 1536);
    k_transpose_out<<<dim3(NW, Cc / 32), 256>>>(z, out);
}

// round 14
// speedup vs baseline: 1.2415x; 1.0135x over previous
#include <cuda_runtime.h>
#include <cuda_fp16.h>
#include <math.h>
#include <stdint.h>

#define B_    8
#define Cc    384
#define Hh    112
#define Ww    112
#define HW    (Hh*Ww)
#define WS_   7
#define Nn    49
#define NH_   12
#define HD    32
#define HID_  1536
#define NW    2048
#define Tt    100352
#define EPS_  1e-5f

// ---------------- scratch (device globals) ---------------------------------
__device__ float  g_xt [(size_t)Tt * Cc];
__device__ float  g_y  [(size_t)Tt * Cc];
__device__ float  g_z  [(size_t)Tt * Cc];
__device__ __half g_xn [(size_t)Tt * Cc];
__device__ __half g_qkv[(size_t)Tt * 3 * Cc];
__device__ __half g_h  [(size_t)Tt * HID_];
__device__ __half g_wq[1152 * 384];
__device__ __half g_wp[384 * 384];
__device__ __half g_w1[1536 * 384];
__device__ __half g_w2[384 * 1536];

// ---------------- ptx helpers ----------------------------------------------
__device__ __forceinline__ uint32_t su32(const void* p) {
    uint32_t a;
    asm("{ .reg .u64 t; cvta.to.shared.u64 t, %1; cvt.u32.u64 %0, t; }" : "=r"(a) : "l"(p));
    return a;
}
__device__ __forceinline__ uint32_t h2u(__half2 h) {
    return *reinterpret_cast<uint32_t*>(&h);
}
__device__ __forceinline__ void cp16(uint32_t d, const void* s) {
    asm volatile("cp.async.cg.shared.global [%0], [%1], 16;" :: "r"(d), "l"(s));
}
__device__ __forceinline__ void cp_commit() { asm volatile("cp.async.commit_group;" ::: "memory"); }
__device__ __forceinline__ void cp_wait2()  { asm volatile("cp.async.wait_group 2;" ::: "memory"); }
__device__ __forceinline__ void cp_wait0()  { asm volatile("cp.async.wait_group 0;" ::: "memory"); }
__device__ __forceinline__ void ldm4(uint32_t* r, uint32_t addr) {
    asm volatile("ldmatrix.sync.aligned.m8n8.x4.shared.b16 {%0,%1,%2,%3}, [%4];"
                 : "=r"(r[0]), "=r"(r[1]), "=r"(r[2]), "=r"(r[3]) : "r"(addr));
}
__device__ __forceinline__ void ldm4t(uint32_t* r, uint32_t addr) {
    asm volatile("ldmatrix.sync.aligned.m8n8.x4.trans.shared.b16 {%0,%1,%2,%3}, [%4];"
                 : "=r"(r[0]), "=r"(r[1]), "=r"(r[2]), "=r"(r[3]) : "r"(addr));
}
__device__ __forceinline__ void mma16816(float* c, const uint32_t* a, uint32_t b0, uint32_t b1) {
    asm volatile(
        "mma.sync.aligned.m16n8k16.row.col.f32.f16.f16.f32 "
        "{%0,%1,%2,%3}, {%4,%5,%6,%7}, {%8,%9}, {%0,%1,%2,%3};"
        : "+f"(c[0]), "+f"(c[1]), "+f"(c[2]), "+f"(c[3])
        : "r"(a[0]), "r"(a[1]), "r"(a[2]), "r"(a[3]), "r"(b0), "r"(b1));
}
__device__ __forceinline__ int div7(int x) { return (x * 9363) >> 16; }

// ---------------- fused (B,C,H,W)->window-token transpose + LN1 ------------
// block: 32 pixels x 384 channels; smem pixel-major stride 385 (conflict-free)
__global__ void __launch_bounds__(256) k_inln(const float* __restrict__ x,
                                              const float* __restrict__ g,
                                              const float* __restrict__ bt,
                                              float* __restrict__ xt,
                                              __half* __restrict__ xn)
{
    extern __shared__ float smf[];   // 32 * 385 floats
    int b = blockIdx.y, hw0 = blockIdx.x * 32;
    int tid = threadIdx.x, lane = tid & 31, warp = tid >> 5;
    const float* xb = x + (size_t)b * Cc * HW + hw0;

    #pragma unroll
    for (int i = 0; i < 48; i++) {
        int e = tid + i * 256;          // 0..12287
        int c = e >> 5, p = e & 31;
        smf[p * 385 + c] = xb[(size_t)c * HW + p];
    }
    __syncthreads();

    #pragma unroll
    for (int pp = 0; pp < 4; pp++) {
        int p = warp * 4 + pp;
        const float* row = smf + p * 385;
        float v[12]; float s = 0.f;
        #pragma unroll
        for (int i = 0; i < 12; i++) { v[i] = row[lane + i * 32]; s += v[i]; }
        #pragma unroll
        for (int o = 16; o; o >>= 1) s += __shfl_xor_sync(0xffffffffu, s, o);
        float m = s * (1.0f / Cc);
        float s2 = 0.f;
        #pragma unroll
        for (int i = 0; i < 12; i++) { float d = v[i] - m; s2 += d * d; }
        #pragma unroll
        for (int o = 16; o; o >>= 1) s2 += __shfl_xor_sync(0xffffffffu, s2, o);
        float r = rsqrtf(s2 * (1.0f / Cc) + EPS_);

        int hw = hw0 + p;
        int h = hw / Ww, w = hw - h * Ww;
        int t = ((b * 256 + (h / WS_) * 16 + (w / WS_)) * Nn) + (h % WS_) * WS_ + (w % WS_);
        float* xr = xt + (size_t)t * Cc;
        __half* nr = xn + (size_t)t * Cc;
        #pragma unroll
        for (int i = 0; i < 12; i++) {
            int c = lane + i * 32;
            xr[c] = v[i];
            nr[c] = __float2half_rn((v[i] - m) * r * g[c] + bt[c]);
        }
    }
}

// ---------------- layernorm -> fp16 (LN2) ----------------------------------
__global__ void k_ln_h(const float* __restrict__ in, const float* __restrict__ g,
                       const float* __restrict__ bt, __half* __restrict__ oh)
{
    int t = blockIdx.x * 8 + threadIdx.y;
    int lane = threadIdx.x;
    const float* row = in + (size_t)t * Cc;
    float v[12]; float s = 0.f;
    #pragma unroll
    for (int i = 0; i < 12; i++) { v[i] = row[lane + i * 32]; s += v[i]; }
    #pragma unroll
    for (int o = 16; o; o >>= 1) s += __shfl_xor_sync(0xffffffffu, s, o);
    float m = s * (1.0f / Cc);
    float s2 = 0.f;
    #pragma unroll
    for (int i = 0; i < 12; i++) { float d = v[i] - m; s2 += d * d; }
    #pragma unroll
    for (int o = 16; o; o >>= 1) s2 += __shfl_xor_sync(0xffffffffu, s2, o);
    float r = rsqrtf(s2 * (1.0f / Cc) + EPS_);
    #pragma unroll
    for (int i = 0; i < 12; i++) {
        int c = lane + i * 32;
        oh[(size_t)t * Cc + c] = __float2half_rn((v[i] - m) * r * g[c] + bt[c]);
    }
}

// ---------------- weight transpose [K][N] -> fp16 [N][K] -------------------
__global__ void k_wprep(const float* __restrict__ W, __half* __restrict__ T, int K, int N)
{
    __shared__ float tile[32][33];
    int n0 = blockIdx.x * 32, k0 = blockIdx.y * 32;
    #pragma unroll
    for (int i = 0; i < 32; i += 8) {
        int k = k0 + threadIdx.y + i, n = n0 + threadIdx.x;
        tile[threadIdx.y + i][threadIdx.x] = W[(size_t)k * N + n];
    }
    __syncthreads();
    #pragma unroll
    for (int i = 0; i < 32; i += 8) {
        int n = n0 + threadIdx.y + i, k = k0 + threadIdx.x;
        T[(size_t)n * K + k] = __float2half_rn(tile[threadIdx.x][threadIdx.y + i]);
    }
}

// ---------------- HMMA GEMM: 256Mx128N tile, warp 64x64, 3-stage ------------
#define STG_ (49152)
__device__ __forceinline__ void load_stage(uint32_t sb, int s, int kc,
    const __half* __restrict__ A, const __half* __restrict__ Bw,
    int m0, int n0, int K, int tid)
{
    uint32_t base = sb + s * STG_;
    #pragma unroll
    for (int i = 0; i < 8; i++) {          // A: 256 rows x 64 cols
        int e = tid + i * 256;
        int r = e >> 3, c = e & 7;
        uint32_t so = (uint32_t)(r * 128 + ((c ^ (r & 7)) << 4));
        cp16(base + so, A + (size_t)(m0 + r) * K + kc + c * 8);
    }
    #pragma unroll
    for (int i = 0; i < 4; i++) {          // B: 128 rows x 64 cols
        int e = tid + i * 256;
        int r = e >> 3, c = e & 7;
        uint32_t so = (uint32_t)(r * 128 + ((c ^ (r & 7)) << 4));
        cp16(base + 32768 + so, Bw + (size_t)(n0 + r) * K + kc + c * 8);
    }
    cp_commit();
}

template<int EPI>
__global__ void __launch_bounds__(256, 1) k_hgemm(
    const __half* __restrict__ A, const __half* __restrict__ Bw,
    const float* __restrict__ bias, const float* __restrict__ res,
    float* __restrict__ outf, __half* __restrict__ outh,
    int N, int K)
{
    extern __shared__ char dsm[];
    uint32_t sb = su32(dsm);
    int tid = threadIdx.x, lane = tid & 31, wid = tid >> 5;
    int m0 = blockIdx.y * 256, n0 = blockIdx.x * 128;
    int wm = (wid >> 1) * 64, wn = (wid & 1) * 64;

    float acc[4][8][4];
    #pragma unroll
    for (int i = 0; i < 4; i++)
        #pragma unroll
        for (int j = 0; j < 8; j++)
            #pragma unroll
            for (int q = 0; q < 4; q++) acc[i][j][q] = 0.f;

    load_stage(sb, 0, 0,   A, Bw, m0, n0, K, tid);
    load_stage(sb, 1, 64,  A, Bw, m0, n0, K, tid);
    load_stage(sb, 2, 128, A, Bw, m0, n0, K, tid);

    int nt = K >> 6;
    int cur = 0;
    for (int t = 0; t < nt; t++) {
        cp_wait2();
        __syncthreads();
        uint32_t abase = sb + cur * STG_;
        uint32_t bbase = abase + 32768;
        #pragma unroll
        for (int s = 0; s < 4; s++) {
            uint32_t a[4][4], b[4][4];
            #pragma unroll
            for (int mi = 0; mi < 4; mi++) {
                int r = wm + mi * 16 + (lane & 15);
                int c = 2 * s + (lane >> 4);
                ldm4(a[mi], abase + r * 128 + ((c ^ (r & 7)) << 4));
            }
            #pragma unroll
            for (int bi = 0; bi < 4; bi++) {
                int r = wn + bi * 16 + (lane & 15);
                int c = 2 * s + (lane >> 4);
                ldm4(b[bi], bbase + r * 128 + ((c ^ (r & 7)) << 4));
            }
            #pragma unroll
            for (int mi = 0; mi < 4; mi++)
                #pragma unroll
                for (int ni = 0; ni < 8; ni++)
                    mma16816(acc[mi][ni], a[mi], b[ni >> 1][ni & 1], b[ni >> 1][(ni & 1) + 2]);
        }
        __syncthreads();
        if (t + 3 < nt) load_stage(sb, cur, (t + 3) * 64, A, Bw, m0, n0, K, tid);
        else cp_commit();
        cur = (cur == 2) ? 0 : cur + 1;
    }

    #pragma unroll
    for (int mi = 0; mi < 4; mi++) {
        #pragma unroll
        for (int ni = 0; ni < 8; ni++) {
            int m = m0 + wm + mi * 16 + (lane >> 2);
            int n = n0 + wn + ni * 8 + 2 * (lane & 3);
            float b0 = bias[n], b1 = bias[n + 1];
            float v0 = acc[mi][ni][0] + b0, v1 = acc[mi][ni][1] + b1;
            float v2 = acc[mi][ni][2] + b0, v3 = acc[mi][ni][3] + b1;
            size_t off0 = (size_t)m * N + n;
            size_t off1 = (size_t)(m + 8) * N + n;
            if (EPI == 2) {
                v0 = 0.5f * v0 * (1.0f + erff(v0 * 0.70710678118654752f));
                v1 = 0.5f * v1 * (1.0f + erff(v1 * 0.70710678118654752f));
                v2 = 0.5f * v2 * (1.0f + erff(v2 * 0.70710678118654752f));
                v3 = 0.5f * v3 * (1.0f + erff(v3 * 0.70710678118654752f));
            }
            if (EPI == 1) {
                float2 r0 = *(const float2*)&res[off0];
                float2 r1 = *(const float2*)&res[off1];
                *(float2*)&outf[off0] = make_float2(v0 + r0.x, v1 + r0.y);
                *(float2*)&outf[off1] = make_float2(v2 + r1.x, v3 + r1.y);
            } else {
                *(__half2*)&outh[off0] = __floats2half2_rn(v0, v1);
                *(__half2*)&outh[off1] = __floats2half2_rn(v2, v3);
            }
        }
    }
}

// ---------------- tensor-core window attention ------------------------------
__global__ void __launch_bounds__(128) k_attn(const __half* __restrict__ qkv,
                                              const float* __restrict__ rpb,
                                              __half* __restrict__ oh)
{
    __shared__ __align__(128) char sm[12288 + 680];
    float* srpb = (float*)(sm + 12288);
    int wb = blockIdx.x, head = blockIdx.y;
    int tid = threadIdx.x, lane = tid & 31, warp = tid >> 5;
    uint32_t sb = su32(sm);

    for (int i = tid; i < 588; i += 128) {
        int mat = i / 196;
        int rem = i - mat * 196;
        int r = rem >> 2, c = rem & 3;
        const __half* src = qkv + ((size_t)(wb * Nn + r)) * 1152 + mat * 384 + head * 32 + c * 8;
        cp16(sb + mat * 4096 + r * 64 + ((c ^ ((r >> 1) & 3)) << 4), src);
    }
    cp_commit();
    uint4 z4 = make_uint4(0, 0, 0, 0);
    for (int i = tid; i < 180; i += 128) {
        int mat = i / 60;
        int rem = i - mat * 60;
        int r = 49 + (rem >> 2), c = rem & 3;
        *(uint4*)(sm + mat * 4096 + r * 64 + ((c ^ ((r >> 1) & 3)) << 4)) = z4;
    }
    for (int i = tid; i < 169; i += 128) srpb[i] = rpb[i * NH_ + head];
    cp_wait0();
    __syncthreads();

    uint32_t qbase = sb, kbase = sb + 4096, vbase = sb + 8192;
    int m0 = warp * 16;

    float sc[8][4];
    #pragma unroll
    for (int j = 0; j < 8; j++)
        #pragma unroll
        for (int q = 0; q < 4; q++) sc[j][q] = 0.f;

    #pragma unroll
    for (int ks = 0; ks < 2; ks++) {
        uint32_t qa[4];
        {
            int g = lane >> 3;
            int r = m0 + (lane & 7) + ((g & 1) ? 8 : 0);
            int c = 2 * ks + (g >> 1);
            ldm4(qa, qbase + r * 64 + ((c ^ ((r >> 1) & 3)) << 4));
        }
        #pragma unroll
        for (int jj = 0; jj < 4; jj++) {
            uint32_t kb[4];
            {
                int g = lane >> 3;
                int r = (2 * jj + (g >> 1)) * 8 + (lane & 7);
                int c = 2 * ks + (g & 1);
                ldm4(kb, kbase + r * 64 + ((c ^ ((r >> 1) & 3)) << 4));
            }
            mma16816(sc[2 * jj],     qa, kb[0], kb[1]);
            mma16816(sc[2 * jj + 1], qa, kb[2], kb[3]);
        }
    }

    int R0 = m0 + (lane >> 2);
    int R1 = R0 + 8;
    int r1a = 0, s1a = 0, r1b = 0, s1b = 0;
    if (R0 < Nn) { r1a = div7(R0); s1a = R0 - 7 * r1a; }
    if (R1 < Nn) { r1b = div7(R1); s1b = R1 - 7 * r1b; }
    const float SC = 0.17677669529663687f;
    #pragma unroll
    for (int j = 0; j < 8; j++) {
        #pragma unroll
        for (int e = 0; e < 2; e++) {
            int col = 8 * j + 2 * (lane & 3) + e;
            float ba, bb;
            if (col < Nn) {
                int r2 = div7(col), s2 = col - 7 * r2;
                ba = srpb[(r1a - r2 + 6) * 13 + (s1a - s2 + 6)];
                bb = srpb[(r1b - r2 + 6) * 13 + (s1b - s2 + 6)];
            } else { ba = -30000.f; bb = -30000.f; }
            sc[j][e]     = sc[j][e] * SC + ba;
            sc[j][e + 2] = sc[j][e + 2] * SC + bb;
        }
    }

    float mx0 = -1e30f, mx1 = -1e30f;
    #pragma unroll
    for (int j = 0; j < 8; j++) {
        mx0 = fmaxf(mx0, fmaxf(sc[j][0], sc[j][1]));
        mx1 = fmaxf(mx1, fmaxf(sc[j][2], sc[j][3]));
    }
    mx0 = fmaxf(mx0, __shfl_xor_sync(0xffffffffu, mx0, 1));
    mx0 = fmaxf(mx0, __shfl_xor_sync(0xffffffffu, mx0, 2));
    mx1 = fmaxf(mx1, __shfl_xor_sync(0xffffffffu, mx1, 1));
    mx1 = fmaxf(mx1, __shfl_xor_sync(0xffffffffu, mx1, 2));
    float sm0 = 0.f, sm1 = 0.f;
    #pragma unroll
    for (int j = 0; j < 8; j++) {
        sc[j][0] = __expf(sc[j][0] - mx0);
        sc[j][1] = __expf(sc[j][1] - mx0);
        sc[j][2] = __expf(sc[j][2] - mx1);
        sc[j][3] = __expf(sc[j][3] - mx1);
        sm0 += sc[j][0] + sc[j][1];
        sm1 += sc[j][2] + sc[j][3];
    }
    sm0 += __shfl_xor_sync(0xffffffffu, sm0, 1);
    sm0 += __shfl_xor_sync(0xffffffffu, sm0, 2);
    sm1 += __shfl_xor_sync(0xffffffffu, sm1, 1);
    sm1 += __shfl_xor_sync(0xffffffffu, sm1, 2);

    uint32_t pa[4][4];
    #pragma unroll
    for (int t = 0; t < 4; t++) {
        pa[t][0] = h2u(__floats2half2_rn(sc[2 * t][0], sc[2 * t][1]));
        pa[t][1] = h2u(__floats2half2_rn(sc[2 * t][2], sc[2 * t][3]));
        pa[t][2] = h2u(__floats2half2_rn(sc[2 * t + 1][0], sc[2 * t + 1][1]));
        pa[t][3] = h2u(__floats2half2_rn(sc[2 * t + 1][2], sc[2 * t + 1][3]));
    }

    float o[4][4];
    #pragma unroll
    for (int j = 0; j < 4; j++)
        #pragma unroll
        for (int q = 0; q < 4; q++) o[j][q] = 0.f;
    #pragma unroll
    for (int t = 0; t < 4; t++) {
        #pragma unroll
        for (int jj = 0; jj < 2; jj++) {
            uint32_t vb[4];
            {
                int g = lane >> 3;
                int r = 16 * t + ((g & 1) ? 8 : 0) + (lane & 7);
                int c = 2 * jj + (g >> 1);
                ldm4t(vb, vbase + r * 64 + ((c ^ ((r >> 1) & 3)) << 4));
            }
            mma16816(o[2 * jj],     pa[t], vb[0], vb[1]);
            mma16816(o[2 * jj + 1], pa[t], vb[2], vb[3]);
        }
    }

    float inv0 = 1.0f / sm0, inv1 = 1.0f / sm1;
    #pragma unroll
    for (int j = 0; j < 4; j++) {
        int col = 8 * j + 2 * (lane & 3);
        if (R0 < Nn) {
            size_t off = (size_t)(wb * Nn + R0) * Cc + head * HD + col;
            *(__half2*)&oh[off] = __floats2half2_rn(o[j][0] * inv0, o[j][1] * inv0);
        }
        if (R1 < Nn) {
            size_t off = (size_t)(wb * Nn + R1) * Cc + head * HD + col;
            *(__half2*)&oh[off] = __floats2half2_rn(o[j][2] * inv1, o[j][3] * inv1);
        }
    }
}

// ---------------- transpose out --------------------------------------------
__global__ void k_transpose_out(const float* __restrict__ z, float* __restrict__ out)
{
    __shared__ float sm[Nn][33];
    int wb = blockIdx.x, c0 = blockIdx.y * 32;
    int b = wb >> 8, wi = (wb >> 4) & 15, wj = wb & 15;
    int tid = threadIdx.x;
    for (int e = tid; e < Nn * 32; e += 256) {
        int p = e >> 5, d = e & 31;
        sm[p][d] = z[(size_t)(wb * Nn + p) * Cc + c0 + d];
    }
    __syncthreads();
    for (int e = tid; e < Nn * 32; e += 256) {
        int d = e / Nn, p = e % Nn;
        int c = c0 + d;
        int h = wi * WS_ + p / WS_, w = wj * WS_ + p % WS_;
        out[(((size_t)b * Cc + c) * Hh + h) * Ww + w] = sm[p][d];
    }
}

// ---------------- launch ----------------------------------------------------
extern "C" void kernel_launch(void* const* d_in, const int* in_sizes, int n_in,
                              void* d_out, int out_size)
{
    const float* x      = (const float*)d_in[0];
    const float* g1     = (const float*)d_in[1];
    const float* b1     = (const float*)d_in[2];
    const float* w_qkv  = (const float*)d_in[3];
    const float* b_qkv  = (const float*)d_in[4];
    const float* rpb    = (const float*)d_in[5];
    const float* w_proj = (const float*)d_in[6];
    const float* b_proj = (const float*)d_in[7];
    const float* g2     = (const float*)d_in[8];
    const float* b2     = (const float*)d_in[9];
    const float* w_fc1  = (const float*)d_in[10];
    const float* b_fc1  = (const float*)d_in[11];
    const float* w_fc2  = (const float*)d_in[12];
    const float* b_fc2  = (const float*)d_in[13];
    float* out = (float*)d_out;

    float *xt, *y, *z;
    __half *xn, *qkv, *hbuf, *wq, *wp, *w1, *w2;
    cudaGetSymbolAddress((void**)&xt, g_xt);
    cudaGetSymbolAddress((void**)&y, g_y);
    cudaGetSymbolAddress((void**)&z, g_z);
    cudaGetSymbolAddress((void**)&xn, g_xn);
    cudaGetSymbolAddress((void**)&qkv, g_qkv);
    cudaGetSymbolAddress((void**)&hbuf, g_h);
    cudaGetSymbolAddress((void**)&wq, g_wq);
    cudaGetSymbolAddress((void**)&wp, g_wp);
    cudaGetSymbolAddress((void**)&w1, g_w1);
    cudaGetSymbolAddress((void**)&w2, g_w2);

    const int SMEM = 3 * STG_;                 // 147456
    const int SMEM_LN = 32 * 385 * 4;          // 49280
    cudaFuncSetAttribute(k_hgemm<0>, cudaFuncAttributeMaxDynamicSharedMemorySize, SMEM);
    cudaFuncSetAttribute(k_hgemm<1>, cudaFuncAttributeMaxDynamicSharedMemorySize, SMEM);
    cudaFuncSetAttribute(k_hgemm<2>, cudaFuncAttributeMaxDynamicSharedMemorySize, SMEM);
    cudaFuncSetAttribute(k_inln, cudaFuncAttributeMaxDynamicSharedMemorySize, SMEM_LN);

    k_wprep<<<dim3(1152 / 32, 384 / 32), dim3(32, 8)>>>(w_qkv, wq, 384, 1152);
    k_wprep<<<dim3(384 / 32, 384 / 32), dim3(32, 8)>>>(w_proj, wp, 384, 384);
    k_wprep<<<dim3(1536 / 32, 384 / 32), dim3(32, 8)>>>(w_fc1, w1, 384, 1536);
    k_wprep<<<dim3(384 / 32, 1536 / 32), dim3(32, 8)>>>(w_fc2, w2, 1536, 384);

    // fused transpose + LN1
    k_inln<<<dim3(HW / 32, B_), 256, SMEM_LN>>>(x, g1, b1, xt, xn);
    // QKV GEMM
    k_hgemm<0><<<dim3(9, Tt / 256), 256, SMEM>>>(xn, wq, b_qkv, nullptr, nullptr, qkv, 1152, 384);
    // attention
    k_attn<<<dim3(NW, NH_), 128>>>(qkv, rpb, xn);
    // proj + residual
    k_hgemm<1><<<dim3(3, Tt / 256), 256, SMEM>>>(xn, wp, b_proj, xt, y, nullptr, 384, 384);
    // LN2
    k_ln_h<<<Tt / 8, dim3(32, 8)>>>(y, g2, b2, xn);
    // fc1 + gelu
    k_hgemm<2><<<dim3(12, Tt / 256), 256, SMEM>>>(xn, w1, b_fc1, nullptr, nullptr, hbuf, 1536, 384);
    // fc2 + residual
    k_hgemm<1><<<dim3(3, Tt / 256), 256, SMEM>>>(hbuf, w2, b_fc2, y, z, nullptr, 384, 1536);
    // transpose back
    k_transpose_out<<<dim3(NW, Cc / 32), 256>>>(z, out);
}